// round 17
// baseline (speedup 1.0000x reference)
#include <cuda_runtime.h>
#include <cuda_fp16.h>
#include <cstdint>

#define B  1024
#define T  100
#define F  300
#define KP 320     /* F padded to 32-multiple */
#define U  512
#define G  2048    /* 4*U */
#define NC 10
#define EPS 1e-3f

// ---- fp16x3 HMMA GEMM config: fine 64x64 tiles for SM load balance ----
#define TMC 64
#define TNC 64
#define BKC 32
#define LDAH 40                       /* padded fp16 stride (conflict-free) */
#define ROWB (LDAH * 2)               /* 80 B row stride */
#define TERMB (TMC * ROWB)            /* 5120 B per operand term tile */
#define STAGEB (4 * TERMB)            /* A0,A1,B0,B1 = 20480 B */
#define SMEM_H (2 * STAGEB)           /* 40960 B */
#define NTILEA ((B * T) / TMC)        /* 1600 precompute row-tiles */
#define NCHUNK 10                     /* precompute chunks (10 timesteps each) */
#define CH_TILES (NTILEA / NCHUNK)    /* 160 row-tiles per chunk */

// ---------------- device scratch ---------------------------------------------------
// batch-indexed arrays live in PERMUTED row order (sorted by len desc)
// A0 and x-splits live in [t*B + p] row order (tile == single t)
__device__ __align__(16) float g_A0[(size_t)B * T * G];
__device__ __align__(16) __half g_x0[(size_t)B * T * KP], g_x1[(size_t)B * T * KP];
__device__ __align__(16) __half g_W0a[(size_t)G * KP], g_W0b[(size_t)G * KP];
__device__ __align__(16) __half g_R0a[(size_t)G * U],  g_R0b[(size_t)G * U];
__device__ __align__(16) __half g_W1a[(size_t)G * U],  g_W1b[(size_t)G * U];
__device__ __align__(16) __half g_R1a[(size_t)G * U],  g_R1b[(size_t)G * U];
__device__ __align__(16) float g_z0[B * G];
__device__ __align__(16) float g_z1a[2][B * G];   // parity double buffer (s2-serial)
__device__ __align__(16) float g_z1b[B * G];
__device__ __align__(16) __half g_h0sa[2][B * U], g_h0sb[2][B * U];  // parity buffers
__device__ __align__(16) __half g_h1sa[B * U], g_h1sb[B * U];
__device__ __align__(16) float g_c0[B * U], g_c1[B * U], g_out[B * U];
__device__ int g_perm[B];        // permuted p -> original b
__device__ int g_plen[B];        // len of permuted row p (descending)
__device__ int g_cnt[T + 1];     // cnt[t] = #rows with len > t
__device__ int g_actA[NTILEA];   // precompute tile flags

__device__ __forceinline__ float sigmf(float x) { return 1.0f / (1.0f + expf(-x)); }

__device__ __forceinline__ void split2(float v, __half& h0, __half& h1)
{
    h0 = __float2half_rn(v);
    h1 = __float2half_rn(v - __half2float(h0));
}

__device__ __forceinline__ void cp16(uint32_t dst, const void* src) {
    asm volatile("cp.async.cg.shared.global [%0], [%1], 16;" :: "r"(dst), "l"(src));
}
__device__ __forceinline__ void cp_commit() { asm volatile("cp.async.commit_group;"); }
__device__ __forceinline__ void cp_wait0()  { asm volatile("cp.async.wait_group 0;"); }

#define MMA16(acc, a, b) \
    asm volatile( \
        "mma.sync.aligned.m16n8k16.row.col.f32.f16.f16.f32 " \
        "{%0,%1,%2,%3},{%4,%5,%6,%7},{%8,%9},{%0,%1,%2,%3};" \
        : "+f"((acc)[0]), "+f"((acc)[1]), "+f"((acc)[2]), "+f"((acc)[3]) \
        : "r"((a)[0]), "r"((a)[1]), "r"((a)[2]), "r"((a)[3]), \
          "r"((b)[0]), "r"((b)[1]))

#define LDSM4(r, addr) \
    asm volatile("ldmatrix.sync.aligned.m8n8.x4.shared.b16 {%0,%1,%2,%3}, [%4];" \
        : "=r"((r)[0]), "=r"((r)[1]), "=r"((r)[2]), "=r"((r)[3]) : "r"(addr))

// ---------------- fp16x3 HMMA GEMM --------------------------------------------------
struct ProbH { const __half *A0, *A1, *B0, *B1; float* C; };
struct GArgsH { ProbH p[2]; };

__global__ __launch_bounds__(128, 5) void gemm_f16x3(GArgsH ga, int N, int K,
                                                     const int* cntp, const int* tilef,
                                                     int yoff)
{
    const int ytile = blockIdx.y + yoff;
    const int m0 = ytile * TMC;
    if (cntp != nullptr && m0 >= *cntp) return;
    if (tilef != nullptr && tilef[ytile] == 0) return;

    extern __shared__ char smem[];
    const uint32_t sb0 = (uint32_t)__cvta_generic_to_shared(smem);

    const ProbH pr = ga.p[blockIdx.z];
    const int tid  = threadIdx.x;
    const int lane = tid & 31;
    const int wid  = tid >> 5;       // 0..3
    const int wm   = wid >> 1;       // 0..1  (32 rows each)
    const int wn   = wid & 1;        // 0..1  (32 cols each)
    const int n0   = blockIdx.x * TNC;
    const int grp  = lane >> 2;      // 0..7
    const int tg   = lane & 3;       // 0..3

    const int lm = lane >> 3, lr = lane & 7;
    const uint32_t aoff = (uint32_t)((((lm & 1) * 8) + lr) * ROWB + (lm >> 1) * 16);
    const uint32_t boff = (uint32_t)((((lm >> 1) * 8) + lr) * ROWB + (lm & 1) * 16);

    auto issue = [&](int stage, int k0) {
        const uint32_t sb = sb0 + (uint32_t)stage * STAGEB;
#pragma unroll
        for (int i = 0; i < 2; i++) {
            const int idx = tid + i * 128;        // 0..255
            const int r = idx >> 2, g = idx & 3;  // row, 16B granule
            const uint32_t doff = (uint32_t)(r * ROWB + g * 16);
            const size_t soffA = (size_t)(m0 + r) * K + k0 + g * 8;
            const size_t soffB = (size_t)(n0 + r) * K + k0 + g * 8;
            cp16(sb + 0 * TERMB + doff, pr.A0 + soffA);
            cp16(sb + 1 * TERMB + doff, pr.A1 + soffA);
            cp16(sb + 2 * TERMB + doff, pr.B0 + soffB);
            cp16(sb + 3 * TERMB + doff, pr.B1 + soffB);
        }
        cp_commit();
    };

    float acc[2][4][4];
#pragma unroll
    for (int i = 0; i < 2; i++)
#pragma unroll
        for (int j = 0; j < 4; j++)
#pragma unroll
            for (int k = 0; k < 4; k++) acc[i][j][k] = 0.f;

    const int NIT = K / BKC;
    issue(0, 0);

    for (int it = 0; it < NIT; ++it) {
        cp_wait0();
        __syncthreads();
        if (it + 1 < NIT) issue((it + 1) & 1, (it + 1) * BKC);

        const uint32_t sst = sb0 + (uint32_t)(it & 1) * STAGEB;
        const uint32_t aBase = sst + (uint32_t)((wm * 32) * ROWB) + aoff;
        const uint32_t bBase = sst + 2 * TERMB + (uint32_t)((wn * 32) * ROWB) + boff;

#pragma unroll
        for (int kk = 0; kk < 2; kk++) {
            uint32_t a0f[2][4], a1f[2][4], b0t[2][4], b1t[2][4];
#pragma unroll
            for (int im = 0; im < 2; im++) {
                const uint32_t ab = aBase + (uint32_t)(im * 16 * ROWB + kk * 32);
                LDSM4(a0f[im], ab);
                LDSM4(a1f[im], ab + TERMB);
            }
#pragma unroll
            for (int jp = 0; jp < 2; jp++) {
                const uint32_t bb = bBase + (uint32_t)(jp * 16 * ROWB + kk * 32);
                LDSM4(b0t[jp], bb);
                LDSM4(b1t[jp], bb + TERMB);
            }
#pragma unroll
            for (int im = 0; im < 2; im++)
#pragma unroll
                for (int jn = 0; jn < 4; jn++) {
                    const uint32_t* b0p = &b0t[jn >> 1][(jn & 1) * 2];
                    const uint32_t* b1p = &b1t[jn >> 1][(jn & 1) * 2];
                    MMA16(acc[im][jn], a1f[im], b0p);   // lo*hi
                    MMA16(acc[im][jn], a0f[im], b1p);   // hi*lo
                    MMA16(acc[im][jn], a0f[im], b0p);   // hi*hi
                }
        }
    }

#pragma unroll
    for (int im = 0; im < 2; im++) {
        const int row0 = m0 + wm * 32 + im * 16 + grp;
#pragma unroll
        for (int jn = 0; jn < 4; jn++) {
            const int col = n0 + wn * 32 + jn * 8 + tg * 2;
            *(float2*)(pr.C + (size_t)row0 * N + col)       = make_float2(acc[im][jn][0], acc[im][jn][1]);
            *(float2*)(pr.C + (size_t)(row0 + 8) * N + col) = make_float2(acc[im][jn][2], acc[im][jn][3]);
        }
    }
}

// ---------------- one-time prep ------------------------------------------------------
__global__ void sort_kernel(const int* __restrict__ mask)
{
    __shared__ int len[B];
    const int b = threadIdx.x;
    int l = 0;
    for (int t = 0; t < T; t++) l += mask[b * T + t];
    len[b] = l;
    __syncthreads();
    int rank = 0;
    for (int j = 0; j < B; j++) {
        const int lj = len[j];
        rank += (lj > l) || (lj == l && j < b);
    }
    g_perm[rank] = b;
    g_plen[rank] = l;
}

__global__ void cnt_kernel()
{
    const int tid = threadIdx.x;   // 1024 threads
    if (tid <= T) {
        int c = 0;
        for (int p = 0; p < B; p++) c += (g_plen[p] > tid);
        g_cnt[tid] = c;
    }
    __syncthreads();
    for (int i = tid; i < NTILEA; i += 1024) {
        const int t  = i >> 4;            // B/TMC = 16 tiles per t
        const int pb = i & 15;
        g_actA[i] = (pb * TMC < g_cnt[t]) ? 1 : 0;
    }
}

__global__ void wsplit2_t(const float* __restrict__ W, __half* __restrict__ t0,
                          __half* __restrict__ t1, int Kd, int N, int Ksrc)
{
    const size_t i = (size_t)blockIdx.x * 256 + threadIdx.x;
    if (i < (size_t)N * Kd) {
        const int n = (int)(i / Kd), k = (int)(i % Kd);
        const float v = (k < Ksrc) ? W[(size_t)k * N + n] : 0.f;
        __half h0, h1;
        split2(v, h0, h1);
        t0[i] = h0; t1[i] = h1;
    }
}

__global__ void xsplit2(const float* __restrict__ x, __half* __restrict__ t0,
                        __half* __restrict__ t1)
{
    const size_t i = (size_t)blockIdx.x * 256 + threadIdx.x;
    if (i < (size_t)B * T * KP) {
        const size_t r = i / KP;       // flat [t*B + p]
        const int c = (int)(i % KP);
        const int t = (int)(r / B), p = (int)(r % B);
        const float v = (c < F) ? x[((size_t)g_perm[p] * T + t) * F + c] : 0.f;
        __half h0, h1;
        split2(v, h0, h1);
        t0[i] = h0; t1[i] = h1;
    }
}

__global__ void init_kernel()
{
    const size_t i = (size_t)blockIdx.x * 256 + threadIdx.x;
    if (i < (size_t)B * G) { g_z0[i] = 0.f; g_z1b[i] = 0.f; }
    if (i < (size_t)B * U) {
        const __half z = __float2half_rn(0.f);
        g_h0sa[0][i] = z; g_h0sb[0][i] = z;
        g_h0sa[1][i] = z; g_h0sb[1][i] = z;
        g_h1sa[i] = z; g_h1sb[i] = z;
        g_c0[i] = 0.f; g_c1[i] = 0.f; g_out[i] = 0.f;
    }
}

// ---------------- unified cell body ----------------------------------------------------
__device__ void cell_body(int layer, int b, int t,
                          const float* __restrict__ za, const float* __restrict__ zb,
                          __half* __restrict__ hda, __half* __restrict__ hdb,
                          const float* __restrict__ gza, const float* __restrict__ bza,
                          const float* __restrict__ gzb, const float* __restrict__ bzb,
                          const float* __restrict__ sg,  const float* __restrict__ sb,
                          const float* __restrict__ bias)
{
    if (t >= g_plen[b]) return;   // uniform per block

    const int tid = threadIdx.x, lane = tid & 31, w = tid >> 5;
    __shared__ float sh1[4][8];
    __shared__ float bc1[4];

    float va[2][4], vb[2][4];
    float s1 = 0.f, p1 = 0.f, s2 = 0.f, p2 = 0.f;
#pragma unroll
    for (int q = 0; q < 2; q++) {
        const int u = tid + q * 256;
#pragma unroll
        for (int gg = 0; gg < 4; gg++) {
            const float x1 = za[gg * U + u];
            const float x2 = zb[gg * U + u];
            va[q][gg] = x1; vb[q][gg] = x2;
            s1 += x1; p1 += x1 * x1; s2 += x2; p2 += x2 * x2;
        }
    }
#pragma unroll
    for (int o = 16; o > 0; o >>= 1) {
        s1 += __shfl_xor_sync(0xffffffffu, s1, o);
        p1 += __shfl_xor_sync(0xffffffffu, p1, o);
        s2 += __shfl_xor_sync(0xffffffffu, s2, o);
        p2 += __shfl_xor_sync(0xffffffffu, p2, o);
    }
    if (lane == 0) { sh1[0][w] = s1; sh1[1][w] = p1; sh1[2][w] = s2; sh1[3][w] = p2; }
    __syncthreads();
    if (tid == 0) {
        float S1 = 0.f, P1 = 0.f, S2 = 0.f, P2 = 0.f;
#pragma unroll
        for (int i = 0; i < 8; i++) { S1 += sh1[0][i]; P1 += sh1[1][i]; S2 += sh1[2][i]; P2 += sh1[3][i]; }
        const float m1 = S1 / (float)G, m2 = S2 / (float)G;
        bc1[0] = m1; bc1[1] = rsqrtf(P1 / (float)G - m1 * m1 + EPS);
        bc1[2] = m2; bc1[3] = rsqrtf(P2 / (float)G - m2 * m2 + EPS);
    }
    __syncthreads();
    const float m1 = bc1[0], r1 = bc1[1], m2 = bc1[2], r2 = bc1[3];

    float* cold = (layer == 0) ? g_c0 : g_c1;
    float cn[2], zo[2];
    float s3 = 0.f, p3 = 0.f;
#pragma unroll
    for (int q = 0; q < 2; q++) {
        const int u = tid + q * 256;
        float zg4[4];
#pragma unroll
        for (int gg = 0; gg < 4; gg++) {
            const int j = gg * U + u;
            zg4[gg] = (va[q][gg] - m1) * r1 * gza[j] + bza[j]
                    + (vb[q][gg] - m2) * r2 * gzb[j] + bzb[j] + bias[j];
        }
        const float c = cold[(size_t)b * U + u];
        const float v = sigmf(zg4[1]) * c + sigmf(zg4[0]) * tanhf(zg4[2]);
        cn[q] = v; zo[q] = zg4[3]; s3 += v; p3 += v * v;
    }
#pragma unroll
    for (int o = 16; o > 0; o >>= 1) {
        s3 += __shfl_xor_sync(0xffffffffu, s3, o);
        p3 += __shfl_xor_sync(0xffffffffu, p3, o);
    }
    __syncthreads();
    if (lane == 0) { sh1[0][w] = s3; sh1[1][w] = p3; }
    __syncthreads();
    if (tid == 0) {
        float S = 0.f, P = 0.f;
#pragma unroll
        for (int i = 0; i < 8; i++) { S += sh1[0][i]; P += sh1[1][i]; }
        const float m = S / (float)U;
        bc1[0] = m;
        bc1[1] = rsqrtf(P / (float)U - m * m + EPS);
    }
    __syncthreads();
    const float mc = bc1[0], rc = bc1[1];
#pragma unroll
    for (int q = 0; q < 2; q++) {
        const int u = tid + q * 256;
        const float cl = (cn[q] - mc) * rc * sg[u] + sb[u];
        const float hn = sigmf(zo[q]) * tanhf(cl);
        __half h0, h1;
        split2(hn, h0, h1);
        hda[(size_t)b * U + u] = h0;
        hdb[(size_t)b * U + u] = h1;
        cold[(size_t)b * U + u] = cl;
        if (layer == 1) g_out[(size_t)b * U + u] = hn;
    }
}

__global__ __launch_bounds__(256) void cell0_kernel(
    const float* rg, const float* rb, const float* kg, const float* kb,
    const float* sg, const float* sb, const float* bias, int t)
{
    const int b = blockIdx.x;
    cell_body(0, b, t,
              g_z0 + (size_t)b * G,
              g_A0 + ((size_t)t * B + b) * G,
              g_h0sa[t & 1], g_h0sb[t & 1],
              rg, rb, kg, kb, sg, sb, bias);
}

__global__ __launch_bounds__(256) void cell1_kernel(
    const float* kg, const float* kb, const float* rg, const float* rb,
    const float* sg, const float* sb, const float* bias, int t)
{
    const int b = blockIdx.x;
    cell_body(1, b, t,
              g_z1b + (size_t)b * G,
              g_z1a[t & 1] + (size_t)b * G,
              g_h1sa, g_h1sb,
              rg, rb, kg, kb, sg, sb, bias);
}

// ---------------- dense + softmax (scatter through perm) ------------------------------
__global__ __launch_bounds__(256) void dense_kernel(const float* __restrict__ Wd,
                                                    const float* __restrict__ bd,
                                                    float* __restrict__ out)
{
    const int b = blockIdx.x, tid = threadIdx.x, lane = tid & 31, w = tid >> 5;
    float p[NC];
#pragma unroll
    for (int c = 0; c < NC; c++) p[c] = 0.f;
    for (int u = tid; u < U; u += 256) {
        const float h = g_out[(size_t)b * U + u];
#pragma unroll
        for (int c = 0; c < NC; c++) p[c] += h * Wd[u * NC + c];
    }
    __shared__ float sh[NC][8];
#pragma unroll
    for (int c = 0; c < NC; c++) {
        float v = p[c];
#pragma unroll
        for (int o = 16; o > 0; o >>= 1) v += __shfl_xor_sync(0xffffffffu, v, o);
        if (lane == 0) sh[c][w] = v;
    }
    __syncthreads();
    if (tid == 0) {
        const int ob = g_perm[b];
        float lg[NC];
        float mx = -1e30f;
#pragma unroll
        for (int c = 0; c < NC; c++) {
            float l = bd[c];
#pragma unroll
            for (int i = 0; i < 8; i++) l += sh[c][i];
            lg[c] = l;
            mx = fmaxf(mx, l);
        }
        float sum = 0.f;
#pragma unroll
        for (int c = 0; c < NC; c++) { lg[c] = expf(lg[c] - mx); sum += lg[c]; }
        const float inv = 1.f / sum;
#pragma unroll
        for (int c = 0; c < NC; c++) out[ob * NC + c] = lg[c] * inv;
    }
}

// ---------------- launch ---------------------------------------------------------------
extern "C" void kernel_launch(void* const* d_in, const int* in_sizes, int n_in,
                              void* d_out, int out_size)
{
    const float* x    = (const float*)d_in[0];
    const int*   mask = (const int*)  d_in[1];
    const float* W0   = (const float*)d_in[2];
    const float* R0   = (const float*)d_in[3];
    const float* b0   = (const float*)d_in[4];
    const float* kg0  = (const float*)d_in[5];
    const float* kb0  = (const float*)d_in[6];
    const float* rg0  = (const float*)d_in[7];
    const float* rb0  = (const float*)d_in[8];
    const float* sg0  = (const float*)d_in[9];
    const float* sb0  = (const float*)d_in[10];
    const float* W1   = (const float*)d_in[11];
    const float* R1   = (const float*)d_in[12];
    const float* b1   = (const float*)d_in[13];
    const float* kg1  = (const float*)d_in[14];
    const float* kb1  = (const float*)d_in[15];
    const float* rg1  = (const float*)d_in[16];
    const float* rb1  = (const float*)d_in[17];
    const float* sg1  = (const float*)d_in[18];
    const float* sb1  = (const float*)d_in[19];
    const float* Wd   = (const float*)d_in[20];
    const float* bd   = (const float*)d_in[21];
    float* out = (float*)d_out;

    float *A0p, *z0p, *z1ap, *z1bp;
    __half *x0, *x1, *W0a, *W0b, *R0a, *R0b, *W1a, *W1b, *R1a, *R1b;
    __half *h0saB, *h0sbB, *h1sa, *h1sb;
    int *cntp, *actAp;
    cudaGetSymbolAddress((void**)&A0p,  g_A0);
    cudaGetSymbolAddress((void**)&z0p,  g_z0);
    cudaGetSymbolAddress((void**)&z1ap, g_z1a);
    cudaGetSymbolAddress((void**)&z1bp, g_z1b);
    cudaGetSymbolAddress((void**)&x0,   g_x0);
    cudaGetSymbolAddress((void**)&x1,   g_x1);
    cudaGetSymbolAddress((void**)&W0a,  g_W0a);
    cudaGetSymbolAddress((void**)&W0b,  g_W0b);
    cudaGetSymbolAddress((void**)&R0a,  g_R0a);
    cudaGetSymbolAddress((void**)&R0b,  g_R0b);
    cudaGetSymbolAddress((void**)&W1a,  g_W1a);
    cudaGetSymbolAddress((void**)&W1b,  g_W1b);
    cudaGetSymbolAddress((void**)&R1a,  g_R1a);
    cudaGetSymbolAddress((void**)&R1b,  g_R1b);
    cudaGetSymbolAddress((void**)&h0saB, g_h0sa);
    cudaGetSymbolAddress((void**)&h0sbB, g_h0sb);
    cudaGetSymbolAddress((void**)&h1sa, g_h1sa);
    cudaGetSymbolAddress((void**)&h1sb, g_h1sb);
    cudaGetSymbolAddress((void**)&cntp, g_cnt);
    cudaGetSymbolAddress((void**)&actAp, g_actA);

    cudaFuncSetAttribute(gemm_f16x3, cudaFuncAttributeMaxDynamicSharedMemorySize, SMEM_H);

    // lazy-init streams + events (handles only; no device memory)
    static cudaStream_t s1 = nullptr, s2 = nullptr, s3 = nullptr;
    static cudaEvent_t evFork = nullptr, evC1 = nullptr, evDone = nullptr;
    static cudaEvent_t evChunk[NCHUNK];
    static cudaEvent_t evH0[T];     // after cell0(t)
    static cudaEvent_t evGA[T];     // after gemm_z1a(t) (read of h0s[t&1] done)
    if (s1 == nullptr) {
        int leastP = 0, greatestP = 0;
        cudaDeviceGetStreamPriorityRange(&leastP, &greatestP);
        cudaStreamCreateWithPriority(&s1, cudaStreamNonBlocking, greatestP);
        cudaStreamCreateWithPriority(&s2, cudaStreamNonBlocking, leastP);
        cudaStreamCreateWithPriority(&s3, cudaStreamNonBlocking, leastP);
        cudaEventCreateWithFlags(&evFork, cudaEventDisableTiming);
        cudaEventCreateWithFlags(&evC1, cudaEventDisableTiming);
        cudaEventCreateWithFlags(&evDone, cudaEventDisableTiming);
        for (int k = 0; k < NCHUNK; k++)
            cudaEventCreateWithFlags(&evChunk[k], cudaEventDisableTiming);
        for (int t = 0; t < T; t++) {
            cudaEventCreateWithFlags(&evH0[t], cudaEventDisableTiming);
            cudaEventCreateWithFlags(&evGA[t], cudaEventDisableTiming);
        }
    }

    // one-time prep (capture stream 0)
    const size_t nW0 = (size_t)G * KP;
    const size_t nRW = (size_t)G * U;
    const size_t nXT = (size_t)B * T * KP;
    init_kernel<<<(B * G + 255) / 256, 256>>>();
    sort_kernel<<<1, B>>>(mask);
    cnt_kernel<<<1, 1024>>>();
    wsplit2_t<<<(unsigned)((nW0 + 255) / 256), 256>>>(W0, W0a, W0b, KP, G, F);
    xsplit2<<<(unsigned)((nXT + 255) / 256), 256>>>(x, x0, x1);

    // fork precompute on s3 (low priority)
    cudaEventRecord(evFork, 0);
    cudaStreamWaitEvent(s3, evFork, 0);
    for (int k = 0; k < NCHUNK; k++) {
        GArgsH a = {};
        a.p[0] = { x0, x1, W0a, W0b, A0p };
        gemm_f16x3<<<dim3(G / TNC, CH_TILES, 1), 128, SMEM_H, s3>>>(
            a, G, KP, nullptr, actAp, k * CH_TILES);
        cudaEventRecord(evChunk[k], s3);
    }

    // remaining weight splits on stream 0, then fork s1/s2
    wsplit2_t<<<(unsigned)((nRW + 255) / 256), 256>>>(R0, R0a, R0b, U, G, U);
    wsplit2_t<<<(unsigned)((nRW + 255) / 256), 256>>>(W1, W1a, W1b, U, G, U);
    wsplit2_t<<<(unsigned)((nRW + 255) / 256), 256>>>(R1, R1a, R1b, U, G, U);
    cudaEventRecord(evFork, 0);
    cudaStreamWaitEvent(s1, evFork, 0);
    cudaStreamWaitEvent(s2, evFork, 0);

    // t = 0 prolog on s1 (z0(0) == 0; z1b(0) == 0 since h1s(0)==0)
    cudaStreamWaitEvent(s1, evChunk[0], 0);
    cell0_kernel<<<B, 256, 0, s1>>>(rg0, rb0, kg0, kb0, sg0, sb0, b0, 0);
    cudaEventRecord(evH0[0], s1);

    for (int t = 0; t < T; t++) {
        const int par = t & 1;
        const __half* h0a = h0saB + (size_t)par * B * U;
        const __half* h0b = h0sbB + (size_t)par * B * U;

        // --- s1 critical chain: gemm_z0(t+1) then cell0(t+1) ---
        if (t + 1 < T) {
            GArgsH aargs = {};
            aargs.p[0] = { h0a, h0b, R0a, R0b, z0p };
            gemm_f16x3<<<dim3(G / TNC, B / TMC, 1), 128, SMEM_H, s1>>>(
                aargs, G, U, cntp + (t + 1), nullptr, 0);
        }

        // --- s2 slack chain: z1a(t), cell1(t), z1b(t+1) ---
        cudaStreamWaitEvent(s2, evH0[t], 0);
        {
            GArgsH bargs = {};
            bargs.p[0] = { h0a, h0b, W1a, W1b, (float*)((char*)z1ap + (size_t)par * B * G * 4) };
            gemm_f16x3<<<dim3(G / TNC, B / TMC, 1), 128, SMEM_H, s2>>>(
                bargs, G, U, cntp + t, nullptr, 0);
        }
        cudaEventRecord(evGA[t], s2);
        cell1_kernel<<<B, 256, 0, s2>>>(kg1, kb1, rg1, rb1, sg1, sb1, b1, t);
        if (t == T - 1) cudaEventRecord(evC1, s2);
        if (t + 1 < T) {
            GArgsH cargs = {};
            cargs.p[0] = { h1sa, h1sb, R1a, R1b, z1bp };
            gemm_f16x3<<<dim3(G / TNC, B / TMC, 1), 128, SMEM_H, s2>>>(
                cargs, G, U, cntp + (t + 1), nullptr, 0);
        }

        // --- s1 continue: cell0(t+1) (WAR on h0s[(t+1)&1] vs gemm_z1a(t-1)) ---
        if (t + 1 < T) {
            if ((t + 1) % (T / NCHUNK) == 0)
                cudaStreamWaitEvent(s1, evChunk[(t + 1) / (T / NCHUNK)], 0);
            if (t >= 1) cudaStreamWaitEvent(s1, evGA[t - 1], 0);
            cell0_kernel<<<B, 256, 0, s1>>>(rg0, rb0, kg0, kb0, sg0, sb0, b0, t + 1);
            cudaEventRecord(evH0[t + 1], s1);
        }
    }

    // dense on s1 after final cell1, then join capture stream
    cudaStreamWaitEvent(s1, evC1, 0);
    dense_kernel<<<B, 256, 0, s1>>>(Wd, bd, out);
    cudaEventRecord(evDone, s1);
    cudaStreamWaitEvent(0, evDone, 0);
}